// round 11
// baseline (speedup 1.0000x reference)
#include <cuda_runtime.h>
#include <cstdint>

// ProdEinsumTC: out[a,b,c,d,g] = (1/3) * sum_{e,f} T1[a,b,c,d,e,f] * T2[b,c,e,f,g]
// T1: (4, 131072, 6, 27) fp32   T2: (131072, 6, 27) fp32   out: (4, 131072, 6, 9)
//
// R8 (final): R7 warp-autonomous issue-once structure, micro-trimmed:
//  - direct STG.32 stores (contiguous 288B run per path/warp: sectors fully
//    covered) -> drops one syncwarp + 9 STS + staged re-read per warp.
//  - launch_bounds(128,13): regs<=39, residency cap 52 warps (smem allows 13
//    blocks at 17.28KB).
// Everything else identical to the 80.38us R7 kernel. This design is at the
// HBM mixed-stream floor (85% DRAM cycles active; remainder is R/W turnaround).

#define BC        786432
#define BC27      ((size_t)BC * 27)
#define BC9       ((size_t)BC * 9)
#define WBC       8                 // bc pairs per warp
#define WARPS     4                 // warps per block
#define NTHREADS  (WARPS * 32)
#define WARP_F    (WBC * 27 * 5)    // 1080 floats per warp region (4xT1 + T2)
#define NORM      (0.3333333333333333f)

__device__ __forceinline__ void cp_async16(uint32_t dst, const void* src) {
    asm volatile("cp.async.cg.shared.global [%0], [%1], 16;\n"
                 :: "r"(dst), "l"(src));
}
__device__ __forceinline__ uint32_t smem_u32(const void* p) {
    uint32_t a;
    asm("{ .reg .u64 t; cvta.to.shared.u64 t, %1; cvt.u32.u64 %0, t; }"
        : "=r"(a) : "l"(p));
    return a;
}

__global__ __launch_bounds__(NTHREADS, 13)
void prod_einsum_kernel(const float* __restrict__ T1,
                        const float* __restrict__ T2,
                        float* __restrict__ out)
{
    __shared__ __align__(16) float smem[WARPS * WARP_F];   // 17280 B

    const int tid  = threadIdx.x;
    const int w    = tid >> 5;
    const int lane = tid & 31;

    float* const swarp = smem + w * WARP_F;
    const uint32_t sw_u32 = smem_u32(swarp);

    const size_t bc0 = ((size_t)blockIdx.x * WARPS + w) * WBC;

    // ---- Stage: 5 segments x 54 float4, all coalesced & 16B-aligned ----
    // Layout: [a=0..3][bcl][27] then [T2][bcl][27]
    #pragma unroll
    for (int a = 0; a < 4; ++a) {
        const float4* __restrict__ g1 =
            (const float4*)(T1 + (size_t)a * BC27 + bc0 * 27);
        cp_async16(sw_u32 + (a * 54 + lane) * 16, g1 + lane);
        if (lane < 22)
            cp_async16(sw_u32 + (a * 54 + 32 + lane) * 16, g1 + 32 + lane);
    }
    {
        const float4* __restrict__ g2 = (const float4*)(T2 + bc0 * 27);
        cp_async16(sw_u32 + (216 + lane) * 16, g2 + lane);
        if (lane < 22)
            cp_async16(sw_u32 + (216 + 32 + lane) * 16, g2 + 32 + lane);
    }
    asm volatile("cp.async.commit_group;\n");
    asm volatile("cp.async.wait_group 0;\n" ::: "memory");
    __syncwarp();

    // ---- Compute: lane = (a, bcl). 54 conflict-free LDS.32, 81 FMA ----
    const int a   = lane >> 3;     // 0..3
    const int bcl = lane & 7;      // 0..7

    const float* __restrict__ t1p = swarp + a * 216 + bcl * 27;  // [d][e][f]
    const float* __restrict__ t2p = swarp + 864 + bcl * 27;      // [e][f][g]

    float acc[9];
    #pragma unroll
    for (int i = 0; i < 9; ++i) acc[i] = 0.0f;

    #pragma unroll
    for (int k = 0; k < 9; ++k) {                 // k = e*3 + f
        const float b0 = t2p[k * 3 + 0];
        const float b1 = t2p[k * 3 + 1];
        const float b2 = t2p[k * 3 + 2];
        #pragma unroll
        for (int d = 0; d < 3; ++d) {
            const float av = t1p[d * 9 + k];
            acc[d * 3 + 0] = fmaf(av, b0, acc[d * 3 + 0]);
            acc[d * 3 + 1] = fmaf(av, b1, acc[d * 3 + 1]);
            acc[d * 3 + 2] = fmaf(av, b2, acc[d * 3 + 2]);
        }
    }

    // ---- Store: direct, 9 contiguous floats/thread; per path each warp
    //      covers a contiguous 288B run -> sectors fully covered, merged
    //      in LTS. No staging, no extra syncwarp. ----
    float* __restrict__ o = out + (size_t)a * BC9 + (bc0 + bcl) * 9;
    #pragma unroll
    for (int j = 0; j < 9; ++j)
        o[j] = acc[j] * NORM;
}

extern "C" void kernel_launch(void* const* d_in, const int* in_sizes, int n_in,
                              void* d_out, int out_size)
{
    const float* T1 = (const float*)d_in[0];
    const float* T2 = (const float*)d_in[1];
    float* out = (float*)d_out;

    const int nblocks = BC / (WARPS * WBC);   // 24576
    prod_einsum_kernel<<<nblocks, NTHREADS>>>(T1, T2, out);
}

// round 14
// speedup vs baseline: 1.1575x; 1.1575x over previous
#include <cuda_runtime.h>
#include <cstdint>

// ProdEinsumTC: out[a,b,c,d,g] = (1/3) * sum_{e,f} T1[a,b,c,d,e,f] * T2[b,c,e,f,g]
// T1: (4, 131072, 6, 27) fp32   T2: (131072, 6, 27) fp32   out: (4, 131072, 6, 9)
//
// FINAL (= R7, the proven 80.38us config): warp-autonomous issue-once structure.
//  - 128-thread blocks (4 warps, 17.28KB smem), launch_bounds(128,12) -> 40 regs,
//    NO spills (launch_bounds 13 forced 32 regs and spilled: 92.6us regression).
//  - Each warp stages its 8-bc tile (4xT1 + T2 = 4.32KB) via coalesced
//    cp.async.cg float4; only __syncwarp barriers -> warps phase-stagger freely.
//  - Compute: lane=(a,bcl), stride-27 conflict-free LDS (gcd(27,32)=1), 81 FMA.
//  - Output staged in smem then written as STG.128 bursts (clean sector-full
//    write stream; direct scattered STG.32 measurably worse).
// Measured at the HBM mixed-stream floor: 85% DRAM cycles, 6.74 TB/s.

#define BC        786432
#define BC27      ((size_t)BC * 27)
#define BC9       ((size_t)BC * 9)
#define WBC       8                 // bc pairs per warp
#define WARPS     4                 // warps per block
#define NTHREADS  (WARPS * 32)
#define WARP_F    (WBC * 27 * 5)    // 1080 floats per warp region (4xT1 + T2)
#define NORM      (0.3333333333333333f)

__device__ __forceinline__ void cp_async16(uint32_t dst, const void* src) {
    asm volatile("cp.async.cg.shared.global [%0], [%1], 16;\n"
                 :: "r"(dst), "l"(src));
}
__device__ __forceinline__ uint32_t smem_u32(const void* p) {
    uint32_t a;
    asm("{ .reg .u64 t; cvta.to.shared.u64 t, %1; cvt.u32.u64 %0, t; }"
        : "=r"(a) : "l"(p));
    return a;
}

__global__ __launch_bounds__(NTHREADS, 12)
void prod_einsum_kernel(const float* __restrict__ T1,
                        const float* __restrict__ T2,
                        float* __restrict__ out)
{
    __shared__ __align__(16) float smem[WARPS * WARP_F];   // 17280 B

    const int tid  = threadIdx.x;
    const int w    = tid >> 5;
    const int lane = tid & 31;

    float* const swarp = smem + w * WARP_F;
    const uint32_t sw_u32 = smem_u32(swarp);

    const size_t bc0 = ((size_t)blockIdx.x * WARPS + w) * WBC;

    // ---- Stage: 5 segments x 54 float4, all coalesced & 16B-aligned ----
    // Layout: [a=0..3][bcl][27] then [T2][bcl][27]
    #pragma unroll
    for (int a = 0; a < 4; ++a) {
        const float4* __restrict__ g1 =
            (const float4*)(T1 + (size_t)a * BC27 + bc0 * 27);
        cp_async16(sw_u32 + (a * 54 + lane) * 16, g1 + lane);
        if (lane < 22)
            cp_async16(sw_u32 + (a * 54 + 32 + lane) * 16, g1 + 32 + lane);
    }
    {
        const float4* __restrict__ g2 = (const float4*)(T2 + bc0 * 27);
        cp_async16(sw_u32 + (216 + lane) * 16, g2 + lane);
        if (lane < 22)
            cp_async16(sw_u32 + (216 + 32 + lane) * 16, g2 + 32 + lane);
    }
    asm volatile("cp.async.commit_group;\n");
    asm volatile("cp.async.wait_group 0;\n" ::: "memory");
    __syncwarp();

    // ---- Compute: lane = (a, bcl). 54 conflict-free LDS.32, 81 FMA ----
    const int a   = lane >> 3;     // 0..3
    const int bcl = lane & 7;      // 0..7

    const float* __restrict__ t1p = swarp + a * 216 + bcl * 27;  // [d][e][f]
    const float* __restrict__ t2p = swarp + 864 + bcl * 27;      // [e][f][g]

    float acc[9];
    #pragma unroll
    for (int i = 0; i < 9; ++i) acc[i] = 0.0f;

    #pragma unroll
    for (int k = 0; k < 9; ++k) {                 // k = e*3 + f
        const float b0 = t2p[k * 3 + 0];
        const float b1 = t2p[k * 3 + 1];
        const float b2 = t2p[k * 3 + 2];
        #pragma unroll
        for (int d = 0; d < 3; ++d) {
            const float av = t1p[d * 9 + k];
            acc[d * 3 + 0] = fmaf(av, b0, acc[d * 3 + 0]);
            acc[d * 3 + 1] = fmaf(av, b1, acc[d * 3 + 1]);
            acc[d * 3 + 2] = fmaf(av, b2, acc[d * 3 + 2]);
        }
    }

    // ---- Store: stage in smem, then STG.128 coalesced ----
    __syncwarp();                   // all compute reads of swarp done
    #pragma unroll
    for (int j = 0; j < 9; ++j)     // stride-9 STS.32: conflict-free
        swarp[lane * 9 + j] = acc[j] * NORM;
    __syncwarp();

    #pragma unroll
    for (int aa = 0; aa < 4; ++aa) {
        float4* __restrict__ o = (float4*)(out + (size_t)aa * BC9 + bc0 * 9);
        if (lane < 18)              // 72 floats = 18 float4 per path
            o[lane] = *(const float4*)(swarp + aa * 72 + lane * 4);
    }
}

extern "C" void kernel_launch(void* const* d_in, const int* in_sizes, int n_in,
                              void* d_out, int out_size)
{
    const float* T1 = (const float*)d_in[0];
    const float* T2 = (const float*)d_in[1];
    float* out = (float*)d_out;

    const int nblocks = BC / (WARPS * WBC);   // 24576
    prod_einsum_kernel<<<nblocks, NTHREADS>>>(T1, T2, out);
}